// round 4
// baseline (speedup 1.0000x reference)
#include <cuda_runtime.h>
#include <cstdint>

// Problem constants
#define BATCH 4
#define SEQ   2048
#define DIM   1024
#define MTOT  (BATCH * SEQ)   // 8192

// GEMM tiling
#define BM 128
#define BN 128
#define BK 16
#define PAD 4   // smem row padding (floats); 132*4=528 B keeps float4 alignment

// Scratch (device globals: allocation-free per harness rules).
// __align__(256): GEMM uses float4 (16B) vector loads; language-level
// alignment of a float array is only 4B, so force it.
__device__ __align__(256) float g_q[(size_t)MTOT * DIM];          // 32 MB
__device__ __align__(256) float g_k[(size_t)MTOT * DIM];          // 32 MB
__device__ __align__(256) float g_v[(size_t)MTOT * DIM];          // 32 MB
__device__ __align__(256) float g_s[(size_t)BATCH * SEQ * SEQ];   // 64 MB (scores -> P in place)

// ---------------------------------------------------------------------------
// Tiled SGEMM: C[M,N] = A[M,K] * B (NN) or A[M,K] * B^T (NT, B is [N,K]).
// 128x128 block tile, BK=16, 256 threads, 8x8 per thread.
// CAUSAL: skip tiles entirely above the diagonal (scores GEMM).
// KLIM:   limit K loop to m0+BM (P is lower-triangular; PV GEMM).
// blockIdx.z = batch; sA/sB/sC are per-batch element strides (0 = shared).
// All dims are multiples of the tiles -> no bounds checks.
// ---------------------------------------------------------------------------
template <int TRANSB, int CAUSAL, int KLIM>
__global__ __launch_bounds__(256, 2)
void sgemm_kernel(const float* __restrict__ A, const float* __restrict__ B,
                  float* __restrict__ C, int K, int N,
                  size_t sA, size_t sB, size_t sC)
{
    const int m0 = blockIdx.y * BM;
    const int n0 = blockIdx.x * BN;
    if (CAUSAL && n0 > m0 + BM - 1) return;   // whole tile masked

    A += (size_t)blockIdx.z * sA;
    B += (size_t)blockIdx.z * sB;
    C += (size_t)blockIdx.z * sC;

    int kend = K;
    if (KLIM) kend = min(K, m0 + BM);   // multiple of BK by construction

    __shared__ float As[BK][BM + PAD];
    __shared__ float Bs[BK][BN + PAD];

    const int tid = threadIdx.x;
    const int tx = tid & 15;        // 0..15 -> 8 output cols (4 + 4 split)
    const int ty = tid >> 4;        // 0..15 -> 8 output rows (4 + 4 split)

    float acc[8][8];
#pragma unroll
    for (int i = 0; i < 8; i++)
#pragma unroll
        for (int j = 0; j < 8; j++) acc[i][j] = 0.f;

    for (int k0 = 0; k0 < kend; k0 += BK) {
        // --- load A tile [BM x BK], store transposed As[k][m] ---
#pragma unroll
        for (int p = 0; p < 2; p++) {
            int row = (tid >> 2) + p * 64;      // 0..127
            int col = (tid & 3) * 4;            // 0,4,8,12
            float4 v = *(const float4*)(A + (size_t)(m0 + row) * K + k0 + col);
            As[col + 0][row] = v.x;
            As[col + 1][row] = v.y;
            As[col + 2][row] = v.z;
            As[col + 3][row] = v.w;
        }
        if (TRANSB) {
            // B is [N,K] row-major; need Bs[k][n] = B[n][k] (same pattern as A)
#pragma unroll
            for (int p = 0; p < 2; p++) {
                int row = (tid >> 2) + p * 64;  // n
                int col = (tid & 3) * 4;        // k
                float4 v = *(const float4*)(B + (size_t)(n0 + row) * K + k0 + col);
                Bs[col + 0][row] = v.x;
                Bs[col + 1][row] = v.y;
                Bs[col + 2][row] = v.z;
                Bs[col + 3][row] = v.w;
            }
        } else {
            // B is [K,N] row-major; tile rows contiguous
#pragma unroll
            for (int p = 0; p < 2; p++) {
                int idx = tid + p * 256;
                int kk = idx >> 5;              // 0..15
                int c4 = (idx & 31) * 4;        // 0..124
                float4 v = *(const float4*)(B + (size_t)(k0 + kk) * N + n0 + c4);
                *(float4*)&Bs[kk][c4] = v;
            }
        }
        __syncthreads();

#pragma unroll
        for (int kk = 0; kk < BK; kk++) {
            float a[8], b[8];
            *(float4*)&a[0] = *(const float4*)&As[kk][ty * 4];
            *(float4*)&a[4] = *(const float4*)&As[kk][ty * 4 + 64];
            *(float4*)&b[0] = *(const float4*)&Bs[kk][tx * 4];
            *(float4*)&b[4] = *(const float4*)&Bs[kk][tx * 4 + 64];
#pragma unroll
            for (int i = 0; i < 8; i++)
#pragma unroll
                for (int j = 0; j < 8; j++)
                    acc[i][j] += a[i] * b[j];
        }
        __syncthreads();
    }

    // --- write back (float4 stores) ---
#pragma unroll
    for (int i = 0; i < 8; i++) {
        int row = m0 + ty * 4 + (i & 3) + ((i >> 2) * 64);
        float* crow = C + (size_t)row * N + n0;
        float4 v0 = make_float4(acc[i][0], acc[i][1], acc[i][2], acc[i][3]);
        float4 v1 = make_float4(acc[i][4], acc[i][5], acc[i][6], acc[i][7]);
        *(float4*)(crow + tx * 4)      = v0;
        *(float4*)(crow + tx * 4 + 64) = v1;
    }
}

// ---------------------------------------------------------------------------
// In-place causal softmax over each row q of S[b] (valid length q+1), then
// zero the masked tail so the downstream NN GEMM needs no masking.
// One block (256 threads) per (q, b) row.
// ---------------------------------------------------------------------------
__global__ void softmax_causal_kernel(float* __restrict__ S, int seq, float scale)
{
    const int q = blockIdx.x;
    float* row = S + ((size_t)blockIdx.y * seq + q) * (size_t)seq;
    const int L = q + 1;
    const int tid = threadIdx.x;
    __shared__ float redm[8];
    __shared__ float reds[8];

    // row max (of raw scores; scale > 0 commutes with max)
    float m = -3.4e38f;
    for (int j = tid; j < L; j += 256) m = fmaxf(m, row[j]);
#pragma unroll
    for (int o = 16; o; o >>= 1) m = fmaxf(m, __shfl_xor_sync(0xffffffffu, m, o));
    if ((tid & 31) == 0) redm[tid >> 5] = m;
    __syncthreads();
    m = fmaxf(fmaxf(fmaxf(redm[0], redm[1]), fmaxf(redm[2], redm[3])),
              fmaxf(fmaxf(redm[4], redm[5]), fmaxf(redm[6], redm[7])));

    // sum of exp
    float s = 0.f;
    for (int j = tid; j < L; j += 256) s += __expf(scale * (row[j] - m));
#pragma unroll
    for (int o = 16; o; o >>= 1) s += __shfl_xor_sync(0xffffffffu, s, o);
    if ((tid & 31) == 0) reds[tid >> 5] = s;
    __syncthreads();
    s = (reds[0] + reds[1]) + (reds[2] + reds[3]) +
        (reds[4] + reds[5]) + (reds[6] + reds[7]);
    const float inv = 1.f / s;

    // write probabilities, zero the masked tail
    for (int j = tid; j < seq; j += 256)
        row[j] = (j < L) ? __expf(scale * (row[j] - m)) * inv : 0.f;
}

// ---------------------------------------------------------------------------
extern "C" void kernel_launch(void* const* d_in, const int* in_sizes, int n_in,
                              void* d_out, int out_size)
{
    const float* x  = (const float*)d_in[0];
    const float* Wq = (const float*)d_in[1];
    const float* Wk = (const float*)d_in[2];
    const float* Wv = (const float*)d_in[3];
    float* out = (float*)d_out;

    // Resolved on the first (non-captured correctness) call; cached after.
    static float *gq = nullptr, *gk = nullptr, *gv = nullptr, *gs = nullptr;
    if (!gq) {
        cudaGetSymbolAddress((void**)&gq, g_q);
        cudaGetSymbolAddress((void**)&gk, g_k);
        cudaGetSymbolAddress((void**)&gv, g_v);
        cudaGetSymbolAddress((void**)&gs, g_s);
    }

    const dim3 blk(256);

    // 1) Q/K/V projections: [8192,1024] x [1024,1024] (NN)
    {
        dim3 grid(DIM / BN, MTOT / BM, 1);
        sgemm_kernel<0, 0, 0><<<grid, blk>>>(x, Wq, gq, DIM, DIM, 0, 0, 0);
        sgemm_kernel<0, 0, 0><<<grid, blk>>>(x, Wk, gk, DIM, DIM, 0, 0, 0);
        sgemm_kernel<0, 0, 0><<<grid, blk>>>(x, Wv, gv, DIM, DIM, 0, 0, 0);
    }

    // 2) Scores: S[b] = Q[b] * K[b]^T (NT), skip tiles above the diagonal
    {
        dim3 grid(SEQ / BN, SEQ / BM, BATCH);
        sgemm_kernel<1, 1, 0><<<grid, blk>>>(gq, gk, gs, DIM, SEQ,
                                             (size_t)SEQ * DIM,
                                             (size_t)SEQ * DIM,
                                             (size_t)SEQ * SEQ);
    }

    // 3) Causal softmax (scale = 1/sqrt(1024) = 1/32), in place -> P
    {
        dim3 grid(SEQ, BATCH);
        softmax_causal_kernel<<<grid, blk>>>(gs, SEQ, 0.03125f);
    }

    // 4) Output: O[b] = P[b] * V[b] (NN), K loop limited to the lower triangle
    {
        dim3 grid(DIM / BN, SEQ / BM, BATCH);
        sgemm_kernel<0, 0, 1><<<grid, blk>>>(gs, gv, out, SEQ, DIM,
                                             (size_t)SEQ * SEQ,
                                             (size_t)SEQ * DIM,
                                             (size_t)SEQ * DIM);
    }
}

// round 6
// speedup vs baseline: 2.3811x; 2.3811x over previous
#include <cuda_runtime.h>
#include <cstdint>

// ---------------------------------------------------------------- problem
#define BATCH 4
#define SEQ   2048
#define DIM   1024
#define MTOT  (BATCH * SEQ)          // 8192

// ---------------------------------------------------------------- GEMM tile
#define TM 128
#define TN 128
#define BK 16
#define LDS 20     // smem row stride (floats): (20*g+t)%32 covers all banks

// ---------------------------------------------------------------- scratch
__device__ __align__(1024) float g_q [(size_t)MTOT * DIM];
__device__ __align__(1024) float g_k [(size_t)MTOT * DIM];
__device__ __align__(1024) float g_v [(size_t)MTOT * DIM];
__device__ __align__(1024) float g_vt[(size_t)MTOT * DIM];          // V^T per batch
__device__ __align__(1024) float g_s [(size_t)BATCH * SEQ * SEQ];   // scores -> P
__device__ __align__(1024) float g_wt[3][(size_t)DIM * DIM];        // W^T x3

// ---------------------------------------------------------------- helpers
__device__ __forceinline__ uint32_t f2tf(float f) {
    uint32_t u; asm("cvt.rna.tf32.f32 %0, %1;" : "=r"(u) : "f"(f)); return u;
}
__device__ __forceinline__ void mma_tf32(float* d, const uint32_t* a, const uint32_t* b) {
    asm volatile(
        "mma.sync.aligned.m16n8k8.row.col.f32.tf32.tf32.f32 "
        "{%0,%1,%2,%3}, {%4,%5,%6,%7}, {%8,%9}, {%0,%1,%2,%3};"
        : "+f"(d[0]), "+f"(d[1]), "+f"(d[2]), "+f"(d[3])
        : "r"(a[0]), "r"(a[1]), "r"(a[2]), "r"(a[3]), "r"(b[0]), "r"(b[1]));
}

// ---------------------------------------------------------------------------
// tf32 tensor-core GEMM: C[M,N] = A[M,K] * B[N,K]^T, both K-major in gmem.
// CTA 128x128, BK=16, 256 threads = 8 warps (2 along M x 4 along N),
// warp tile 64x32 via m16n8k8 (4x4 mma tiles). Producer LDG.128 -> cvt.rna
// -> STS.128; register-staged next tile overlaps LDG with mma.
// CAUSAL: skip tiles fully above the diagonal. KLIM: K limited to m0+TM.
// ---------------------------------------------------------------------------
template <int CAUSAL, int KLIM>
__global__ __launch_bounds__(256, 2)
void mma_gemm(const float* __restrict__ A, const float* __restrict__ B,
              float* __restrict__ C, int K, int lda, int ldb, int ldc,
              size_t sA, size_t sB, size_t sC)
{
    const int m0 = blockIdx.y * TM;
    const int n0 = blockIdx.x * TN;
    if (CAUSAL && n0 > m0 + TM - 1) return;

    A += (size_t)blockIdx.z * sA;
    B += (size_t)blockIdx.z * sB;
    C += (size_t)blockIdx.z * sC;

    const int kend  = KLIM ? (m0 + TM) : K;
    const int niter = kend / BK;

    __shared__ __align__(16) float As[TM * LDS];
    __shared__ __align__(16) float Bs[TN * LDS];

    const int tid    = threadIdx.x;
    const int lane   = tid & 31;
    const int wid    = tid >> 5;
    const int warp_m = (wid & 1) * 64;       // 0 / 64
    const int warp_n = (wid >> 1) * 32;      // 0 / 32 / 64 / 96
    const int gid    = lane >> 2;            // 0..7
    const int tig    = lane & 3;             // 0..3

    // producer mapping: thread -> (row = tid>>2, +64), (kcol = (tid&3)*4)
    const int prow = tid >> 2;               // 0..63
    const int pcol = (tid & 3) * 4;          // 0,4,8,12

    const float* Ag0 = A + (size_t)(m0 + prow)      * lda + pcol;
    const float* Ag1 = A + (size_t)(m0 + prow + 64) * lda + pcol;
    const float* Bg0 = B + (size_t)(n0 + prow)      * ldb + pcol;
    const float* Bg1 = B + (size_t)(n0 + prow + 64) * ldb + pcol;

    float4 ra0 = *(const float4*)(Ag0);
    float4 ra1 = *(const float4*)(Ag1);
    float4 rb0 = *(const float4*)(Bg0);
    float4 rb1 = *(const float4*)(Bg1);

    float acc[4][4][4];
#pragma unroll
    for (int i = 0; i < 4; i++)
#pragma unroll
        for (int j = 0; j < 4; j++)
#pragma unroll
            for (int r = 0; r < 4; r++) acc[i][j][r] = 0.f;

    uint32_t* const sA32 = (uint32_t*)As;
    uint32_t* const sB32 = (uint32_t*)Bs;

    for (int it = 0; it < niter; ++it) {
        // stage current tile into smem (tf32-rounded)
        *(uint4*)&sA32[(prow)      * LDS + pcol] = make_uint4(f2tf(ra0.x), f2tf(ra0.y), f2tf(ra0.z), f2tf(ra0.w));
        *(uint4*)&sA32[(prow + 64) * LDS + pcol] = make_uint4(f2tf(ra1.x), f2tf(ra1.y), f2tf(ra1.z), f2tf(ra1.w));
        *(uint4*)&sB32[(prow)      * LDS + pcol] = make_uint4(f2tf(rb0.x), f2tf(rb0.y), f2tf(rb0.z), f2tf(rb0.w));
        *(uint4*)&sB32[(prow + 64) * LDS + pcol] = make_uint4(f2tf(rb1.x), f2tf(rb1.y), f2tf(rb1.z), f2tf(rb1.w));
        __syncthreads();

        // prefetch next tile (overlaps the mma work below)
        if (it + 1 < niter) {
            const int ko = (it + 1) * BK;
            ra0 = *(const float4*)(Ag0 + ko);
            ra1 = *(const float4*)(Ag1 + ko);
            rb0 = *(const float4*)(Bg0 + ko);
            rb1 = *(const float4*)(Bg1 + ko);
        }

#pragma unroll
        for (int k8 = 0; k8 < 2; ++k8) {
            const int kc = k8 * 8 + tig;
            uint32_t a[4][4], b[4][2];
#pragma unroll
            for (int i = 0; i < 4; ++i) {
                const int r = warp_m + i * 16 + gid;
                a[i][0] = sA32[(r)     * LDS + kc];
                a[i][1] = sA32[(r + 8) * LDS + kc];
                a[i][2] = sA32[(r)     * LDS + kc + 4];
                a[i][3] = sA32[(r + 8) * LDS + kc + 4];
            }
#pragma unroll
            for (int j = 0; j < 4; ++j) {
                const int r = warp_n + j * 8 + gid;
                b[j][0] = sB32[r * LDS + kc];
                b[j][1] = sB32[r * LDS + kc + 4];
            }
#pragma unroll
            for (int i = 0; i < 4; ++i)
#pragma unroll
                for (int j = 0; j < 4; ++j)
                    mma_tf32(acc[i][j], a[i], b[j]);
        }
        __syncthreads();
    }

    // epilogue: c0,c1 at (row gid, col 2*tig,+1); c2,c3 at row gid+8
#pragma unroll
    for (int i = 0; i < 4; ++i) {
        const int r0 = m0 + warp_m + i * 16 + gid;
#pragma unroll
        for (int j = 0; j < 4; ++j) {
            const int c0 = n0 + warp_n + j * 8 + 2 * tig;
            *(float2*)(C + (size_t)(r0)     * ldc + c0) = make_float2(acc[i][j][0], acc[i][j][1]);
            *(float2*)(C + (size_t)(r0 + 8) * ldc + c0) = make_float2(acc[i][j][2], acc[i][j][3]);
        }
    }
}

// ---------------------------------------------------------------------------
// 32x32 tiled transpose: out[C,R] = in[R,C]^T (per batch slice in grid.z)
// ---------------------------------------------------------------------------
__global__ void transpose_kernel(const float* __restrict__ in, float* __restrict__ out,
                                 int R, int C, size_t sIn, size_t sOut)
{
    __shared__ float t[32][33];
    in  += (size_t)blockIdx.z * sIn;
    out += (size_t)blockIdx.z * sOut;
    const int c0 = blockIdx.x * 32, r0 = blockIdx.y * 32;
    const int tx = threadIdx.x, ty = threadIdx.y;      // 32 x 8
#pragma unroll
    for (int i = 0; i < 32; i += 8)
        t[ty + i][tx] = in[(size_t)(r0 + ty + i) * C + c0 + tx];
    __syncthreads();
#pragma unroll
    for (int i = 0; i < 32; i += 8)
        out[(size_t)(c0 + ty + i) * R + r0 + tx] = t[tx][ty + i];
}

// ---------------------------------------------------------------------------
// In-place causal softmax per row; zeroes the masked tail.
// ---------------------------------------------------------------------------
__global__ void softmax_causal_kernel(float* __restrict__ S, int seq, float scale)
{
    const int q = blockIdx.x;
    float* row = S + ((size_t)blockIdx.y * seq + q) * (size_t)seq;
    const int L = q + 1;
    const int tid = threadIdx.x;
    __shared__ float redm[8], reds[8];

    float m = -3.4e38f;
    for (int j = tid; j < L; j += 256) m = fmaxf(m, row[j]);
#pragma unroll
    for (int o = 16; o; o >>= 1) m = fmaxf(m, __shfl_xor_sync(0xffffffffu, m, o));
    if ((tid & 31) == 0) redm[tid >> 5] = m;
    __syncthreads();
    m = fmaxf(fmaxf(fmaxf(redm[0], redm[1]), fmaxf(redm[2], redm[3])),
              fmaxf(fmaxf(redm[4], redm[5]), fmaxf(redm[6], redm[7])));

    float s = 0.f;
    for (int j = tid; j < L; j += 256) s += __expf(scale * (row[j] - m));
#pragma unroll
    for (int o = 16; o; o >>= 1) s += __shfl_xor_sync(0xffffffffu, s, o);
    if ((tid & 31) == 0) reds[tid >> 5] = s;
    __syncthreads();
    s = (reds[0] + reds[1]) + (reds[2] + reds[3]) +
        (reds[4] + reds[5]) + (reds[6] + reds[7]);
    const float inv = 1.f / s;

    for (int j = tid; j < seq; j += 256)
        row[j] = (j < L) ? __expf(scale * (row[j] - m)) * inv : 0.f;
}

// ---------------------------------------------------------------------------
extern "C" void kernel_launch(void* const* d_in, const int* in_sizes, int n_in,
                              void* d_out, int out_size)
{
    const float* x  = (const float*)d_in[0];
    const float* Wq = (const float*)d_in[1];
    const float* Wk = (const float*)d_in[2];
    const float* Wv = (const float*)d_in[3];
    float* out = (float*)d_out;

    static float *gq = nullptr, *gk, *gv, *gvt, *gs, *gwt;
    if (!gq) {   // first call is outside graph capture
        cudaGetSymbolAddress((void**)&gq,  g_q);
        cudaGetSymbolAddress((void**)&gk,  g_k);
        cudaGetSymbolAddress((void**)&gv,  g_v);
        cudaGetSymbolAddress((void**)&gvt, g_vt);
        cudaGetSymbolAddress((void**)&gs,  g_s);
        cudaGetSymbolAddress((void**)&gwt, g_wt);
    }
    float* wtq = gwt;
    float* wtk = gwt + (size_t)DIM * DIM;
    float* wtv = gwt + 2 * (size_t)DIM * DIM;

    // 0) W^T (K-major B operands for the projections)
    {
        dim3 g(DIM / 32, DIM / 32, 1), b(32, 8);
        transpose_kernel<<<g, b>>>(Wq, wtq, DIM, DIM, 0, 0);
        transpose_kernel<<<g, b>>>(Wk, wtk, DIM, DIM, 0, 0);
        transpose_kernel<<<g, b>>>(Wv, wtv, DIM, DIM, 0, 0);
    }
    // 1) projections: [8192x1024] = x * W   (A=x, B=W^T, both K-major)
    {
        dim3 g(DIM / TN, MTOT / TM, 1);
        mma_gemm<0,0><<<g, 256>>>(x, wtq, gq, DIM, DIM, DIM, DIM, 0, 0, 0);
        mma_gemm<0,0><<<g, 256>>>(x, wtk, gk, DIM, DIM, DIM, DIM, 0, 0, 0);
        mma_gemm<0,0><<<g, 256>>>(x, wtv, gv, DIM, DIM, DIM, DIM, 0, 0, 0);
    }
    // 2) V^T per batch (B operand of the PV GEMM)
    {
        dim3 g(DIM / 32, SEQ / 32, BATCH), b(32, 8);
        transpose_kernel<<<g, b>>>(gv, gvt, SEQ, DIM, (size_t)SEQ * DIM, (size_t)SEQ * DIM);
    }
    // 3) scores: S[b] = Q[b] * K[b]^T (K already [N,K] K-major); skip masked tiles
    {
        dim3 g(SEQ / TN, SEQ / TM, BATCH);
        mma_gemm<1,0><<<g, 256>>>(gq, gk, gs, DIM, DIM, DIM, SEQ,
                                  (size_t)SEQ * DIM, (size_t)SEQ * DIM,
                                  (size_t)SEQ * SEQ);
    }
    // 4) causal softmax (scale 1/32), in place -> P (masked tail zeroed)
    {
        dim3 g(SEQ, BATCH);
        softmax_causal_kernel<<<g, 256>>>(gs, SEQ, 0.03125f);
    }
    // 5) O[b] = P[b] * V[b]  (B = V^T [dim, seq] K-major, K limited to m0+TM)
    {
        dim3 g(DIM / TN, SEQ / TM, BATCH);
        mma_gemm<0,1><<<g, 256>>>(gs, gvt, out, SEQ, SEQ, SEQ, DIM,
                                  (size_t)SEQ * SEQ, (size_t)SEQ * DIM,
                                  (size_t)SEQ * DIM);
    }
}

// round 7
// speedup vs baseline: 3.0273x; 1.2714x over previous
#include <cuda_runtime.h>
#include <cstdint>

// ---------------------------------------------------------------- problem
#define BATCH 4
#define SEQ   2048
#define DIM   1024
#define MTOT  (BATCH * SEQ)          // 8192

// ---------------------------------------------------------------- GEMM tile
#define TM 128
#define TN 128
#define BK 16
#define LDS 20     // smem row stride (floats); conflict-free for STS + ldmatrix

// ---------------------------------------------------------------- scratch
__device__ __align__(1024) float g_qkv[3][(size_t)MTOT * DIM];      // Q,K,V
__device__ __align__(1024) float g_vt[(size_t)MTOT * DIM];          // V^T per batch
__device__ __align__(1024) float g_s [(size_t)BATCH * SEQ * SEQ];   // scores -> P
__device__ __align__(1024) float g_wt[3][(size_t)DIM * DIM];        // W^T x3

// ---------------------------------------------------------------- helpers
__device__ __forceinline__ uint32_t f2tf(float f) {
    uint32_t u; asm("cvt.rna.tf32.f32 %0, %1;" : "=r"(u) : "f"(f)); return u;
}
__device__ __forceinline__ uint32_t smem_u32(const void* p) {
    uint32_t a;
    asm("{ .reg .u64 t; cvta.to.shared.u64 t, %1; cvt.u32.u64 %0, t; }" : "=r"(a) : "l"(p));
    return a;
}
__device__ __forceinline__ void mma_tf32(float* d, const uint32_t* a, const uint32_t* b) {
    asm volatile(
        "mma.sync.aligned.m16n8k8.row.col.f32.tf32.tf32.f32 "
        "{%0,%1,%2,%3}, {%4,%5,%6,%7}, {%8,%9}, {%0,%1,%2,%3};"
        : "+f"(d[0]), "+f"(d[1]), "+f"(d[2]), "+f"(d[3])
        : "r"(a[0]), "r"(a[1]), "r"(a[2]), "r"(a[3]), "r"(b[0]), "r"(b[1]));
}
__device__ __forceinline__ void ldmx4(uint32_t* r, uint32_t addr) {
    asm volatile("ldmatrix.sync.aligned.m8n8.x4.shared.b16 {%0,%1,%2,%3}, [%4];"
                 : "=r"(r[0]), "=r"(r[1]), "=r"(r[2]), "=r"(r[3]) : "r"(addr));
}

// ---------------------------------------------------------------------------
// tf32 tensor-core GEMM: C[M,N] = A[M,K] * B[N,K]^T, both K-major in gmem.
// CTA 128x128, BK=16, 8 warps (2 x 4), warp tile 64x32 via m16n8k8.
// Double-buffered smem (one bar/iter); fragments via ldmatrix.x4 (an 8x4-tf32
// tile as an 8x8-b16 ldmatrix matrix gives exactly the mma tf32 thread map).
// CAUSAL: skip tiles fully above the diagonal. KLIM: K limited to m0+TM.
// ---------------------------------------------------------------------------
template <int CAUSAL, int KLIM>
__global__ __launch_bounds__(256, 2)
void mma_gemm(const float* __restrict__ A, const float* __restrict__ B,
              float* __restrict__ C, int K, int lda, int ldb, int ldc,
              size_t sA, size_t sB, size_t sC)
{
    const int m0 = blockIdx.y * TM;
    const int n0 = blockIdx.x * TN;
    if (CAUSAL && n0 > m0 + TM - 1) return;

    A += (size_t)blockIdx.z * sA;
    B += (size_t)blockIdx.z * sB;
    C += (size_t)blockIdx.z * sC;

    const int kend  = KLIM ? (m0 + TM) : K;
    const int niter = kend / BK;

    __shared__ __align__(16) uint32_t As[2][TM * LDS];
    __shared__ __align__(16) uint32_t Bs[2][TN * LDS];

    const int tid    = threadIdx.x;
    const int lane   = tid & 31;
    const int wid    = tid >> 5;
    const int warp_m = (wid & 1) * 64;       // 0 / 64
    const int warp_n = (wid >> 1) * 32;      // 0 / 32 / 64 / 96
    const int gid    = lane >> 2;            // 0..7
    const int tig    = lane & 3;             // 0..3

    // ldmatrix per-lane byte offsets (matrix = lane>>3, row = lane&7)
    const int msel = lane >> 3, mrow = lane & 7;
    const uint32_t offA = ((warp_m + (msel & 1) * 8 + mrow) * LDS + (msel >> 1) * 4) * 4;
    const uint32_t offB = ((warp_n + (msel >> 1) * 8 + mrow) * LDS + (msel & 1) * 4) * 4;
    const uint32_t AsB = smem_u32(As);
    const uint32_t BsB = smem_u32(Bs);
    const uint32_t BUFA = TM * LDS * 4;      // bytes per A buffer
    const uint32_t BUFB = TN * LDS * 4;

    // producer mapping: row = tid>>2 (+64), kcol = (tid&3)*4
    const int prow = tid >> 2;
    const int pcol = (tid & 3) * 4;

    const float* Ag0 = A + (size_t)(m0 + prow)      * lda + pcol;
    const float* Ag1 = A + (size_t)(m0 + prow + 64) * lda + pcol;
    const float* Bg0 = B + (size_t)(n0 + prow)      * ldb + pcol;
    const float* Bg1 = B + (size_t)(n0 + prow + 64) * ldb + pcol;

    float acc[4][4][4];
#pragma unroll
    for (int i = 0; i < 4; i++)
#pragma unroll
        for (int j = 0; j < 4; j++)
#pragma unroll
            for (int r = 0; r < 4; r++) acc[i][j][r] = 0.f;

    // prologue: tile 0 -> regs -> buf 0
    float4 ra0 = *(const float4*)(Ag0);
    float4 ra1 = *(const float4*)(Ag1);
    float4 rb0 = *(const float4*)(Bg0);
    float4 rb1 = *(const float4*)(Bg1);
    *(uint4*)&As[0][(prow)      * LDS + pcol] = make_uint4(f2tf(ra0.x), f2tf(ra0.y), f2tf(ra0.z), f2tf(ra0.w));
    *(uint4*)&As[0][(prow + 64) * LDS + pcol] = make_uint4(f2tf(ra1.x), f2tf(ra1.y), f2tf(ra1.z), f2tf(ra1.w));
    *(uint4*)&Bs[0][(prow)      * LDS + pcol] = make_uint4(f2tf(rb0.x), f2tf(rb0.y), f2tf(rb0.z), f2tf(rb0.w));
    *(uint4*)&Bs[0][(prow + 64) * LDS + pcol] = make_uint4(f2tf(rb1.x), f2tf(rb1.y), f2tf(rb1.z), f2tf(rb1.w));
    __syncthreads();

    for (int it = 0; it < niter; ++it) {
        const int b = it & 1;
        const uint32_t aBuf = AsB + b * BUFA;
        const uint32_t bBuf = BsB + b * BUFB;

        // prefetch tile it+1 (LDG latency hidden by the MMA block)
        if (it + 1 < niter) {
            const int ko = (it + 1) * BK;
            ra0 = *(const float4*)(Ag0 + ko);
            ra1 = *(const float4*)(Ag1 + ko);
            rb0 = *(const float4*)(Bg0 + ko);
            rb1 = *(const float4*)(Bg1 + ko);
        }

#pragma unroll
        for (int k8 = 0; k8 < 2; ++k8) {
            uint32_t a[4][4], bf[4][2];
#pragma unroll
            for (int i = 0; i < 4; ++i)
                ldmx4(a[i], aBuf + offA + i * (16 * LDS * 4) + k8 * 32);
#pragma unroll
            for (int jp = 0; jp < 2; ++jp) {
                uint32_t r[4];
                ldmx4(r, bBuf + offB + jp * (16 * LDS * 4) + k8 * 32);
                bf[2 * jp][0]     = r[0]; bf[2 * jp][1]     = r[1];
                bf[2 * jp + 1][0] = r[2]; bf[2 * jp + 1][1] = r[3];
            }
#pragma unroll
            for (int i = 0; i < 4; ++i)
#pragma unroll
                for (int j = 0; j < 4; ++j)
                    mma_tf32(acc[i][j], a[i], bf[j]);
        }

        // stage tile it+1 into the other buffer
        if (it + 1 < niter) {
            const int nb = b ^ 1;
            *(uint4*)&As[nb][(prow)      * LDS + pcol] = make_uint4(f2tf(ra0.x), f2tf(ra0.y), f2tf(ra0.z), f2tf(ra0.w));
            *(uint4*)&As[nb][(prow + 64) * LDS + pcol] = make_uint4(f2tf(ra1.x), f2tf(ra1.y), f2tf(ra1.z), f2tf(ra1.w));
            *(uint4*)&Bs[nb][(prow)      * LDS + pcol] = make_uint4(f2tf(rb0.x), f2tf(rb0.y), f2tf(rb0.z), f2tf(rb0.w));
            *(uint4*)&Bs[nb][(prow + 64) * LDS + pcol] = make_uint4(f2tf(rb1.x), f2tf(rb1.y), f2tf(rb1.z), f2tf(rb1.w));
        }
        __syncthreads();
    }

    // epilogue: c0,c1 at (row gid, col 2*tig); c2,c3 at row gid+8
#pragma unroll
    for (int i = 0; i < 4; ++i) {
        const int r0 = m0 + warp_m + i * 16 + gid;
#pragma unroll
        for (int j = 0; j < 4; ++j) {
            const int c0 = n0 + warp_n + j * 8 + 2 * tig;
            *(float2*)(C + (size_t)(r0)     * ldc + c0) = make_float2(acc[i][j][0], acc[i][j][1]);
            *(float2*)(C + (size_t)(r0 + 8) * ldc + c0) = make_float2(acc[i][j][2], acc[i][j][3]);
        }
    }
}

// ---------------------------------------------------------------------------
// 32x32 tiled transpose: out[C,R] = in[R,C]^T (per batch slice in grid.z)
// ---------------------------------------------------------------------------
__global__ void transpose_kernel(const float* __restrict__ in, float* __restrict__ out,
                                 int R, int C, size_t sIn, size_t sOut)
{
    __shared__ float t[32][33];
    in  += (size_t)blockIdx.z * sIn;
    out += (size_t)blockIdx.z * sOut;
    const int c0 = blockIdx.x * 32, r0 = blockIdx.y * 32;
    const int tx = threadIdx.x, ty = threadIdx.y;      // 32 x 8
#pragma unroll
    for (int i = 0; i < 32; i += 8)
        t[ty + i][tx] = in[(size_t)(r0 + ty + i) * C + c0 + tx];
    __syncthreads();
#pragma unroll
    for (int i = 0; i < 32; i += 8)
        out[(size_t)(c0 + ty + i) * R + r0 + tx] = t[tx][ty + i];
}

// ---------------------------------------------------------------------------
// In-place causal softmax per row; zeroes the masked tail.
// ---------------------------------------------------------------------------
__global__ void softmax_causal_kernel(float* __restrict__ S, int seq, float scale)
{
    const int q = blockIdx.x;
    float* row = S + ((size_t)blockIdx.y * seq + q) * (size_t)seq;
    const int L = q + 1;
    const int tid = threadIdx.x;
    __shared__ float redm[8], reds[8];

    float m = -3.4e38f;
    for (int j = tid; j < L; j += 256) m = fmaxf(m, row[j]);
#pragma unroll
    for (int o = 16; o; o >>= 1) m = fmaxf(m, __shfl_xor_sync(0xffffffffu, m, o));
    if ((tid & 31) == 0) redm[tid >> 5] = m;
    __syncthreads();
    m = fmaxf(fmaxf(fmaxf(redm[0], redm[1]), fmaxf(redm[2], redm[3])),
              fmaxf(fmaxf(redm[4], redm[5]), fmaxf(redm[6], redm[7])));

    float s = 0.f;
    for (int j = tid; j < L; j += 256) s += __expf(scale * (row[j] - m));
#pragma unroll
    for (int o = 16; o; o >>= 1) s += __shfl_xor_sync(0xffffffffu, s, o);
    if ((tid & 31) == 0) reds[tid >> 5] = s;
    __syncthreads();
    s = (reds[0] + reds[1]) + (reds[2] + reds[3]) +
        (reds[4] + reds[5]) + (reds[6] + reds[7]);
    const float inv = 1.f / s;

    for (int j = tid; j < seq; j += 256)
        row[j] = (j < L) ? __expf(scale * (row[j] - m)) * inv : 0.f;
}

// ---------------------------------------------------------------------------
extern "C" void kernel_launch(void* const* d_in, const int* in_sizes, int n_in,
                              void* d_out, int out_size)
{
    const float* x  = (const float*)d_in[0];
    const float* Wq = (const float*)d_in[1];
    const float* Wk = (const float*)d_in[2];
    const float* Wv = (const float*)d_in[3];
    float* out = (float*)d_out;

    static float *gqkv = nullptr, *gvt, *gs, *gwt;
    if (!gqkv) {   // first call is outside graph capture
        cudaGetSymbolAddress((void**)&gqkv, g_qkv);
        cudaGetSymbolAddress((void**)&gvt,  g_vt);
        cudaGetSymbolAddress((void**)&gs,   g_s);
        cudaGetSymbolAddress((void**)&gwt,  g_wt);
    }
    float* gq = gqkv;
    float* gk = gqkv + (size_t)MTOT * DIM;
    float* gv = gqkv + 2 * (size_t)MTOT * DIM;

    // 0) W^T (K-major B operands for the projections)
    {
        dim3 g(DIM / 32, DIM / 32, 1), b(32, 8);
        transpose_kernel<<<g, b>>>(Wq, gwt,                         DIM, DIM, 0, 0);
        transpose_kernel<<<g, b>>>(Wk, gwt + (size_t)DIM * DIM,     DIM, DIM, 0, 0);
        transpose_kernel<<<g, b>>>(Wv, gwt + 2 * (size_t)DIM * DIM, DIM, DIM, 0, 0);
    }
    // 1) fused projections: z selects {Wq,Wk,Wv} -> {Q,K,V}
    {
        dim3 g(DIM / TN, MTOT / TM, 3);
        mma_gemm<0,0><<<g, 256>>>(x, gwt, gqkv, DIM, DIM, DIM, DIM,
                                  0, (size_t)DIM * DIM, (size_t)MTOT * DIM);
    }
    // 2) V^T per batch (B operand of the PV GEMM)
    {
        dim3 g(DIM / 32, SEQ / 32, BATCH), b(32, 8);
        transpose_kernel<<<g, b>>>(gv, gvt, SEQ, DIM, (size_t)SEQ * DIM, (size_t)SEQ * DIM);
    }
    // 3) scores: S[b] = Q[b] * K[b]^T; skip fully-masked tiles
    {
        dim3 g(SEQ / TN, SEQ / TM, BATCH);
        mma_gemm<1,0><<<g, 256>>>(gq, gk, gs, DIM, DIM, DIM, SEQ,
                                  (size_t)SEQ * DIM, (size_t)SEQ * DIM,
                                  (size_t)SEQ * SEQ);
    }
    // 4) causal softmax (scale 1/32), in place -> P (masked tail zeroed)
    {
        dim3 g(SEQ, BATCH);
        softmax_causal_kernel<<<g, 256>>>(gs, SEQ, 0.03125f);
    }
    // 5) O[b] = P[b] * V[b]  (B = V^T [dim, seq] K-major, K limited to m0+TM)
    {
        dim3 g(DIM / TN, SEQ / TM, BATCH);
        mma_gemm<0,1><<<g, 256>>>(gs, gvt, out, SEQ, SEQ, SEQ, DIM,
                                  (size_t)SEQ * SEQ, (size_t)SEQ * DIM,
                                  (size_t)SEQ * DIM);
    }
}

// round 8
// speedup vs baseline: 3.3231x; 1.0977x over previous
#include <cuda_runtime.h>
#include <cuda_fp16.h>
#include <cstdint>

// ---------------------------------------------------------------- problem
#define BATCH 4
#define SEQ   2048
#define DIM   1024
#define MTOT  (BATCH * SEQ)          // 8192

// ---------------------------------------------------------------- GEMM tile
#define TM 128
#define TN 128
#define BK 16
#define LDSH 24    // smem row stride (halves) = 48B: 8-row ldmatrix banks distinct

// ---------------------------------------------------------------- scratch
__device__ __align__(1024) float g_qkv[3][(size_t)MTOT * DIM];      // Q,K,V
__device__ __align__(1024) float g_vt[(size_t)MTOT * DIM];          // V^T per batch
__device__ __align__(1024) float g_s [(size_t)BATCH * SEQ * SEQ];   // scores -> P
__device__ __align__(1024) float g_wt[3][(size_t)DIM * DIM];        // W^T x3

// ---------------------------------------------------------------- helpers
__device__ __forceinline__ uint32_t f2h2(float lo, float hi) {   // packed {lo,hi}
    uint32_t r; asm("cvt.rn.f16x2.f32 %0, %1, %2;" : "=r"(r) : "f"(hi), "f"(lo)); return r;
}
__device__ __forceinline__ uint32_t smem_u32(const void* p) {
    uint32_t a;
    asm("{ .reg .u64 t; cvta.to.shared.u64 t, %1; cvt.u32.u64 %0, t; }" : "=r"(a) : "l"(p));
    return a;
}
__device__ __forceinline__ void mma_f16(float* d, const uint32_t* a, const uint32_t* b) {
    asm volatile(
        "mma.sync.aligned.m16n8k16.row.col.f32.f16.f16.f32 "
        "{%0,%1,%2,%3}, {%4,%5,%6,%7}, {%8,%9}, {%0,%1,%2,%3};"
        : "+f"(d[0]), "+f"(d[1]), "+f"(d[2]), "+f"(d[3])
        : "r"(a[0]), "r"(a[1]), "r"(a[2]), "r"(a[3]), "r"(b[0]), "r"(b[1]));
}
__device__ __forceinline__ void ldmx4(uint32_t* r, uint32_t addr) {
    asm volatile("ldmatrix.sync.aligned.m8n8.x4.shared.b16 {%0,%1,%2,%3}, [%4];"
                 : "=r"(r[0]), "=r"(r[1]), "=r"(r[2]), "=r"(r[3]) : "r"(addr));
}

// ---------------------------------------------------------------------------
// fp16 tensor-core GEMM (fp32 accum): C[M,N] = A[M,K] * B[N,K]^T, fp32 gmem.
// CTA 128x128, BK=16, 8 warps (2 x 4), warp tile 64x32 via m16n8k16.
// Producer: LDG.128 x2 -> cvt.rn.f16x2 -> one STS.128 per row-segment.
// Fragments via ldmatrix.x4; double-buffered smem, one barrier per iter.
// CAUSAL: skip tiles fully above the diagonal. KLIM: K limited to m0+TM.
// ---------------------------------------------------------------------------
template <int CAUSAL, int KLIM>
__global__ __launch_bounds__(256, 2)
void mma_gemm(const float* __restrict__ A, const float* __restrict__ B,
              float* __restrict__ C, int K, int lda, int ldb, int ldc,
              size_t sA, size_t sB, size_t sC)
{
    const int m0 = blockIdx.y * TM;
    const int n0 = blockIdx.x * TN;
    if (CAUSAL && n0 > m0 + TM - 1) return;

    A += (size_t)blockIdx.z * sA;
    B += (size_t)blockIdx.z * sB;
    C += (size_t)blockIdx.z * sC;

    const int kend  = KLIM ? (m0 + TM) : K;
    const int niter = kend / BK;

    __shared__ __align__(16) __half As[2][TM * LDSH];
    __shared__ __align__(16) __half Bs[2][TN * LDSH];

    const int tid    = threadIdx.x;
    const int lane   = tid & 31;
    const int wid    = tid >> 5;
    const int warp_m = (wid & 1) * 64;       // 0 / 64
    const int warp_n = (wid >> 1) * 32;      // 0 / 32 / 64 / 96
    const int gid    = lane >> 2;            // 0..7
    const int tig    = lane & 3;             // 0..3

    // ldmatrix per-lane addressing: matrix msel = lane>>3 selects
    // (row += (msel&1)*8, col += (msel>>1)*8 halves); mrow = lane&7.
    const int msel = lane >> 3, mrow = lane & 7;
    const uint32_t off  = (((msel & 1) * 8 + mrow) * LDSH + (msel >> 1) * 8) * 2;
    const uint32_t offA = warp_m * LDSH * 2 + off;
    const uint32_t offB = warp_n * LDSH * 2 + off;
    const uint32_t AsB  = smem_u32(As);
    const uint32_t BsB  = smem_u32(Bs);
    const uint32_t BUF  = TM * LDSH * 2;     // 6144 B per buffer

    // producer mapping: row = tid>>1 (0..127), cols = (tid&1)*8 .. +7 floats
    const int prow = tid >> 1;
    const int pcol = (tid & 1) * 8;
    const float* Ag = A + (size_t)(m0 + prow) * lda + pcol;
    const float* Bg = B + (size_t)(n0 + prow) * ldb + pcol;
    const uint32_t stsOff = (prow * LDSH + pcol) * 2;   // bytes

    float acc[4][4][4];
#pragma unroll
    for (int i = 0; i < 4; i++)
#pragma unroll
        for (int j = 0; j < 4; j++)
#pragma unroll
            for (int r = 0; r < 4; r++) acc[i][j][r] = 0.f;

    // prologue: tile 0 -> buf 0
    float4 ua = *(const float4*)(Ag);
    float4 va = *(const float4*)(Ag + 4);
    float4 ub = *(const float4*)(Bg);
    float4 vb = *(const float4*)(Bg + 4);
    *(uint4*)((char*)As[0] + stsOff) =
        make_uint4(f2h2(ua.x, ua.y), f2h2(ua.z, ua.w), f2h2(va.x, va.y), f2h2(va.z, va.w));
    *(uint4*)((char*)Bs[0] + stsOff) =
        make_uint4(f2h2(ub.x, ub.y), f2h2(ub.z, ub.w), f2h2(vb.x, vb.y), f2h2(vb.z, vb.w));
    __syncthreads();

    for (int it = 0; it < niter; ++it) {
        const int b = it & 1;
        const uint32_t aBuf = AsB + b * BUF;
        const uint32_t bBuf = BsB + b * BUF;

        // prefetch tile it+1 (LDG latency hidden by the MMA block)
        if (it + 1 < niter) {
            const int ko = (it + 1) * BK;
            ua = *(const float4*)(Ag + ko);
            va = *(const float4*)(Ag + ko + 4);
            ub = *(const float4*)(Bg + ko);
            vb = *(const float4*)(Bg + ko + 4);
        }

        uint32_t a[4][4], bf[4][2];
#pragma unroll
        for (int i = 0; i < 4; ++i)
            ldmx4(a[i], aBuf + offA + i * (16 * LDSH * 2));
#pragma unroll
        for (int jp = 0; jp < 2; ++jp) {
            uint32_t r[4];
            ldmx4(r, bBuf + offB + jp * (16 * LDSH * 2));
            bf[2 * jp][0]     = r[0]; bf[2 * jp + 1][0] = r[1];
            bf[2 * jp][1]     = r[2]; bf[2 * jp + 1][1] = r[3];
        }
#pragma unroll
        for (int i = 0; i < 4; ++i)
#pragma unroll
            for (int j = 0; j < 4; ++j)
                mma_f16(acc[i][j], a[i], bf[j]);

        // stage tile it+1 into the other buffer
        if (it + 1 < niter) {
            const int nb = b ^ 1;
            *(uint4*)((char*)As[nb] + stsOff) =
                make_uint4(f2h2(ua.x, ua.y), f2h2(ua.z, ua.w), f2h2(va.x, va.y), f2h2(va.z, va.w));
            *(uint4*)((char*)Bs[nb] + stsOff) =
                make_uint4(f2h2(ub.x, ub.y), f2h2(ub.z, ub.w), f2h2(vb.x, vb.y), f2h2(vb.z, vb.w));
        }
        __syncthreads();
    }

    // epilogue: c0,c1 at (row gid, col 2*tig); c2,c3 at row gid+8
#pragma unroll
    for (int i = 0; i < 4; ++i) {
        const int r0 = m0 + warp_m + i * 16 + gid;
#pragma unroll
        for (int j = 0; j < 4; ++j) {
            const int c0 = n0 + warp_n + j * 8 + 2 * tig;
            *(float2*)(C + (size_t)(r0)     * ldc + c0) = make_float2(acc[i][j][0], acc[i][j][1]);
            *(float2*)(C + (size_t)(r0 + 8) * ldc + c0) = make_float2(acc[i][j][2], acc[i][j][3]);
        }
    }
}

// ---------------------------------------------------------------------------
// 32x32 tiled transpose: out[C,R] = in[R,C]^T (per batch slice in grid.z)
// ---------------------------------------------------------------------------
__global__ void transpose_kernel(const float* __restrict__ in, float* __restrict__ out,
                                 int R, int C, size_t sIn, size_t sOut)
{
    __shared__ float t[32][33];
    in  += (size_t)blockIdx.z * sIn;
    out += (size_t)blockIdx.z * sOut;
    const int c0 = blockIdx.x * 32, r0 = blockIdx.y * 32;
    const int tx = threadIdx.x, ty = threadIdx.y;      // 32 x 8
#pragma unroll
    for (int i = 0; i < 32; i += 8)
        t[ty + i][tx] = in[(size_t)(r0 + ty + i) * C + c0 + tx];
    __syncthreads();
#pragma unroll
    for (int i = 0; i < 32; i += 8)
        out[(size_t)(c0 + ty + i) * R + r0 + tx] = t[tx][ty + i];
}

// ---------------------------------------------------------------------------
// In-place causal softmax per row; zeroes the masked tail.
// ---------------------------------------------------------------------------
__global__ void softmax_causal_kernel(float* __restrict__ S, int seq, float scale)
{
    const int q = blockIdx.x;
    float* row = S + ((size_t)blockIdx.y * seq + q) * (size_t)seq;
    const int L = q + 1;
    const int tid = threadIdx.x;
    __shared__ float redm[8], reds[8];

    float m = -3.4e38f;
    for (int j = tid; j < L; j += 256) m = fmaxf(m, row[j]);
#pragma unroll
    for (int o = 16; o; o >>= 1) m = fmaxf(m, __shfl_xor_sync(0xffffffffu, m, o));
    if ((tid & 31) == 0) redm[tid >> 5] = m;
    __syncthreads();
    m = fmaxf(fmaxf(fmaxf(redm[0], redm[1]), fmaxf(redm[2], redm[3])),
              fmaxf(fmaxf(redm[4], redm[5]), fmaxf(redm[6], redm[7])));

    float s = 0.f;
    for (int j = tid; j < L; j += 256) s += __expf(scale * (row[j] - m));
#pragma unroll
    for (int o = 16; o; o >>= 1) s += __shfl_xor_sync(0xffffffffu, s, o);
    if ((tid & 31) == 0) reds[tid >> 5] = s;
    __syncthreads();
    s = (reds[0] + reds[1]) + (reds[2] + reds[3]) +
        (reds[4] + reds[5]) + (reds[6] + reds[7]);
    const float inv = 1.f / s;

    for (int j = tid; j < seq; j += 256)
        row[j] = (j < L) ? __expf(scale * (row[j] - m)) * inv : 0.f;
}

// ---------------------------------------------------------------------------
extern "C" void kernel_launch(void* const* d_in, const int* in_sizes, int n_in,
                              void* d_out, int out_size)
{
    const float* x  = (const float*)d_in[0];
    const float* Wq = (const float*)d_in[1];
    const float* Wk = (const float*)d_in[2];
    const float* Wv = (const float*)d_in[3];
    float* out = (float*)d_out;

    static float *gqkv = nullptr, *gvt, *gs, *gwt;
    if (!gqkv) {   // first call is outside graph capture
        cudaGetSymbolAddress((void**)&gqkv, g_qkv);
        cudaGetSymbolAddress((void**)&gvt,  g_vt);
        cudaGetSymbolAddress((void**)&gs,   g_s);
        cudaGetSymbolAddress((void**)&gwt,  g_wt);
    }
    float* gq = gqkv;
    float* gk = gqkv + (size_t)MTOT * DIM;
    float* gv = gqkv + 2 * (size_t)MTOT * DIM;

    // 0) W^T (K-major B operands for the projections)
    {
        dim3 g(DIM / 32, DIM / 32, 1), b(32, 8);
        transpose_kernel<<<g, b>>>(Wq, gwt,                         DIM, DIM, 0, 0);
        transpose_kernel<<<g, b>>>(Wk, gwt + (size_t)DIM * DIM,     DIM, DIM, 0, 0);
        transpose_kernel<<<g, b>>>(Wv, gwt + 2 * (size_t)DIM * DIM, DIM, DIM, 0, 0);
    }
    // 1) fused projections: z selects {Wq,Wk,Wv} -> {Q,K,V}
    {
        dim3 g(DIM / TN, MTOT / TM, 3);
        mma_gemm<0,0><<<g, 256>>>(x, gwt, gqkv, DIM, DIM, DIM, DIM,
                                  0, (size_t)DIM * DIM, (size_t)MTOT * DIM);
    }
    // 2) V^T per batch (B operand of the PV GEMM)
    {
        dim3 g(DIM / 32, SEQ / 32, BATCH), b(32, 8);
        transpose_kernel<<<g, b>>>(gv, gvt, SEQ, DIM, (size_t)SEQ * DIM, (size_t)SEQ * DIM);
    }
    // 3) scores: S[b] = Q[b] * K[b]^T; skip fully-masked tiles
    {
        dim3 g(SEQ / TN, SEQ / TM, BATCH);
        mma_gemm<1,0><<<g, 256>>>(gq, gk, gs, DIM, DIM, DIM, SEQ,
                                  (size_t)SEQ * DIM, (size_t)SEQ * DIM,
                                  (size_t)SEQ * SEQ);
    }
    // 4) causal softmax (scale 1/32), in place -> P (masked tail zeroed)
    {
        dim3 g(SEQ, BATCH);
        softmax_causal_kernel<<<g, 256>>>(gs, SEQ, 0.03125f);
    }
    // 5) O[b] = P[b] * V[b]  (B = V^T [dim, seq] K-major, K limited to m0+TM)
    {
        dim3 g(DIM / TN, SEQ / TM, BATCH);
        mma_gemm<0,1><<<g, 256>>>(gs, gvt, out, SEQ, SEQ, SEQ, DIM,
                                  (size_t)SEQ * SEQ, (size_t)SEQ * DIM,
                                  (size_t)SEQ * DIM);
    }
}

// round 9
// speedup vs baseline: 4.7206x; 1.4205x over previous
#include <cuda_runtime.h>
#include <cuda_fp16.h>
#include <cstdint>

// ---------------------------------------------------------------- problem
#define BATCH 4
#define SEQ   2048
#define DIM   1024
#define MTOT  (BATCH * SEQ)          // 8192

// ---------------------------------------------------------------- GEMM tile
#define TM   128
#define TN   256
#define BKH  32                      // K halves per stage (2 x k16)
#define SREG 40                      // smem row stride in halves (80 B)
#define ABUF (TM * SREG * 2)         // 10240 B per A buffer
#define BBUF (TN * SREG * 2)         // 20480 B per B buffer
#define SMEM_TOTAL (2 * ABUF + 2 * BBUF)   // 61440 B (dynamic, opt-in)

// ---------------------------------------------------------------- scratch
__device__ __align__(1024) __half g_xh  [(size_t)MTOT * DIM];        // x fp16
__device__ __align__(1024) __half g_wth [3][(size_t)DIM * DIM];      // W^T fp16
__device__ __align__(1024) __half g_qkvh[3][(size_t)MTOT * DIM];     // Q,K,V fp16
__device__ __align__(1024) __half g_vth [(size_t)MTOT * DIM];        // V^T fp16
__device__ __align__(1024) float  g_s   [(size_t)BATCH * SEQ * SEQ]; // scores fp32
__device__ __align__(1024) __half g_ph  [(size_t)BATCH * SEQ * SEQ]; // P fp16

// ---------------------------------------------------------------- helpers
__device__ __forceinline__ uint32_t f2h2(float lo, float hi) {   // packed {lo,hi}
    uint32_t r; asm("cvt.rn.f16x2.f32 %0, %1, %2;" : "=r"(r) : "f"(hi), "f"(lo)); return r;
}
__device__ __forceinline__ uint32_t smem_u32(const void* p) {
    uint32_t a;
    asm("{ .reg .u64 t; cvta.to.shared.u64 t, %1; cvt.u32.u64 %0, t; }" : "=r"(a) : "l"(p));
    return a;
}
__device__ __forceinline__ void mma_f16(float* d, const uint32_t* a, const uint32_t* b) {
    asm volatile(
        "mma.sync.aligned.m16n8k16.row.col.f32.f16.f16.f32 "
        "{%0,%1,%2,%3}, {%4,%5,%6,%7}, {%8,%9}, {%0,%1,%2,%3};"
        : "+f"(d[0]), "+f"(d[1]), "+f"(d[2]), "+f"(d[3])
        : "r"(a[0]), "r"(a[1]), "r"(a[2]), "r"(a[3]), "r"(b[0]), "r"(b[1]));
}
__device__ __forceinline__ void ldmx4(uint32_t* r, uint32_t addr) {
    asm volatile("ldmatrix.sync.aligned.m8n8.x4.shared.b16 {%0,%1,%2,%3}, [%4];"
                 : "=r"(r[0]), "=r"(r[1]), "=r"(r[2]), "=r"(r[3]) : "r"(addr));
}

// ---------------------------------------------------------------------------
// fp16 tensor-core GEMM (fp32 accum): C[M,N] = A[M,K] * B[N,K]^T.
// A,B fp16 K-major in gmem. CTA 128x256, warp tile 64x64, 8 warps, BK=32.
// Double-buffered smem, ldmatrix.x4 fragments, one barrier per stage.
// HOUT: write C as fp16 (else fp32). CAUSAL / KLIM as before.
// ---------------------------------------------------------------------------
template <int CAUSAL, int KLIM, int HOUT>
__global__ __launch_bounds__(256, 1)
void mma_gemm(const __half* __restrict__ A, const __half* __restrict__ B,
              void* __restrict__ Cv, int K, int lda, int ldb, int ldc,
              size_t sA, size_t sB, size_t sC)
{
    const int m0 = blockIdx.y * TM;
    const int n0 = blockIdx.x * TN;
    if (CAUSAL && n0 > m0 + TM - 1) return;

    A += (size_t)blockIdx.z * sA;
    B += (size_t)blockIdx.z * sB;

    const int kend  = KLIM ? (m0 + TM) : K;
    const int niter = kend / BKH;

    extern __shared__ __align__(16) char smem[];
    char* const aBase = smem;                 // 2 x ABUF
    char* const bBase = smem + 2 * ABUF;      // 2 x BBUF

    const int tid    = threadIdx.x;
    const int lane   = tid & 31;
    const int wid    = tid >> 5;
    const int warp_m = (wid & 1) * 64;        // 0 / 64
    const int warp_n = (wid >> 1) * 64;       // 0 / 64 / 128 / 192
    const int gid    = lane >> 2;
    const int tig    = lane & 3;

    // ldmatrix lane addressing (validated mapping from R7/R8)
    const int msel = lane >> 3, mrow = lane & 7;
    const uint32_t off  = (((msel & 1) * 8 + mrow) * SREG + (msel >> 1) * 8) * 2;
    const uint32_t offA = warp_m * SREG * 2 + off;
    const uint32_t offB = warp_n * SREG * 2 + off;
    const uint32_t AsB  = smem_u32(aBase);
    const uint32_t BsB  = smem_u32(bBase);

    // producer: row = tid>>2 (0..63), half-col = (tid&3)*8 (16B chunks)
    const int prow = tid >> 2;
    const int pch  = (tid & 3) * 8;
    const __half* Ag = A + (size_t)(m0 + prow) * lda + pch;
    const __half* Bg = B + (size_t)(n0 + prow) * ldb + pch;
    const uint32_t sts = (prow * SREG + pch) * 2;   // byte offset in buffer

    float acc[4][8][4];
#pragma unroll
    for (int i = 0; i < 4; i++)
#pragma unroll
        for (int j = 0; j < 8; j++)
#pragma unroll
            for (int r = 0; r < 4; r++) acc[i][j][r] = 0.f;

    uint4 ra[2], rb[4];
    // prologue: tile 0 -> buf 0
    ra[0] = *(const uint4*)(Ag);
    ra[1] = *(const uint4*)(Ag + (size_t)64 * lda);
#pragma unroll
    for (int r = 0; r < 4; ++r) rb[r] = *(const uint4*)(Bg + (size_t)(64 * r) * ldb);
    *(uint4*)(aBase + sts)                  = ra[0];
    *(uint4*)(aBase + sts + 64 * SREG * 2)  = ra[1];
#pragma unroll
    for (int r = 0; r < 4; ++r) *(uint4*)(bBase + sts + r * 64 * SREG * 2) = rb[r];
    __syncthreads();

    for (int it = 0; it < niter; ++it) {
        const int b = it & 1;
        const uint32_t aBuf = AsB + b * ABUF;
        const uint32_t bBuf = BsB + b * BBUF;

        if (it + 1 < niter) {          // prefetch next stage (hidden by mma)
            const int ko = (it + 1) * BKH;
            ra[0] = *(const uint4*)(Ag + ko);
            ra[1] = *(const uint4*)(Ag + (size_t)64 * lda + ko);
#pragma unroll
            for (int r = 0; r < 4; ++r)
                rb[r] = *(const uint4*)(Bg + (size_t)(64 * r) * ldb + ko);
        }

#pragma unroll
        for (int kc = 0; kc < 2; ++kc) {
            uint32_t af[4][4], bf[8][2];
#pragma unroll
            for (int i = 0; i < 4; ++i)
                ldmx4(af[i], aBuf + offA + i * (16 * SREG * 2) + kc * 32);
#pragma unroll
            for (int jp = 0; jp < 4; ++jp) {
                uint32_t r[4];
                ldmx4(r, bBuf + offB + jp * (16 * SREG * 2) + kc * 32);
                bf[2 * jp][0]     = r[0]; bf[2 * jp + 1][0] = r[1];
                bf[2 * jp][1]     = r[2]; bf[2 * jp + 1][1] = r[3];
            }
#pragma unroll
            for (int i = 0; i < 4; ++i)
#pragma unroll
                for (int j = 0; j < 8; ++j)
                    mma_f16(acc[i][j], af[i], bf[j]);
        }

        if (it + 1 < niter) {          // stage next tile into the other buffer
            char* aD = aBase + (b ^ 1) * ABUF;
            char* bD = bBase + (b ^ 1) * BBUF;
            *(uint4*)(aD + sts)                 = ra[0];
            *(uint4*)(aD + sts + 64 * SREG * 2) = ra[1];
#pragma unroll
            for (int r = 0; r < 4; ++r) *(uint4*)(bD + sts + r * 64 * SREG * 2) = rb[r];
        }
        __syncthreads();
    }

    // epilogue
    if (HOUT) {
        __half* Ch = (__half*)Cv + (size_t)blockIdx.z * sC;
#pragma unroll
        for (int i = 0; i < 4; ++i) {
            const int r0 = m0 + warp_m + i * 16 + gid;
#pragma unroll
            for (int j = 0; j < 8; ++j) {
                const int c0 = n0 + warp_n + j * 8 + 2 * tig;
                *(uint32_t*)(Ch + (size_t)(r0)     * ldc + c0) = f2h2(acc[i][j][0], acc[i][j][1]);
                *(uint32_t*)(Ch + (size_t)(r0 + 8) * ldc + c0) = f2h2(acc[i][j][2], acc[i][j][3]);
            }
        }
    } else {
        float* Cf = (float*)Cv + (size_t)blockIdx.z * sC;
#pragma unroll
        for (int i = 0; i < 4; ++i) {
            const int r0 = m0 + warp_m + i * 16 + gid;
#pragma unroll
            for (int j = 0; j < 8; ++j) {
                const int c0 = n0 + warp_n + j * 8 + 2 * tig;
                *(float2*)(Cf + (size_t)(r0)     * ldc + c0) = make_float2(acc[i][j][0], acc[i][j][1]);
                *(float2*)(Cf + (size_t)(r0 + 8) * ldc + c0) = make_float2(acc[i][j][2], acc[i][j][3]);
            }
        }
    }
}

// ---------------------------------------------------------------------------
// fp32 -> fp16 elementwise (vectorized)
// ---------------------------------------------------------------------------
__global__ void f2h_kernel(const float4* __restrict__ in, uint2* __restrict__ out, int n4)
{
    int i = blockIdx.x * blockDim.x + threadIdx.x;
    if (i < n4) {
        float4 v = in[i];
        out[i] = make_uint2(f2h2(v.x, v.y), f2h2(v.z, v.w));
    }
}

// ---------------------------------------------------------------------------
// fp32 -> fp16 transpose: out[C,R] = half(in[R,C]^T)
// ---------------------------------------------------------------------------
__global__ void transpose_f2h(const float* __restrict__ in, __half* __restrict__ out,
                              int R, int C)
{
    __shared__ float t[32][33];
    const int c0 = blockIdx.x * 32, r0 = blockIdx.y * 32;
    const int tx = threadIdx.x, ty = threadIdx.y;      // 32 x 8
#pragma unroll
    for (int i = 0; i < 32; i += 8)
        t[ty + i][tx] = in[(size_t)(r0 + ty + i) * C + c0 + tx];
    __syncthreads();
#pragma unroll
    for (int i = 0; i < 32; i += 8)
        out[(size_t)(c0 + ty + i) * R + r0 + tx] = __float2half_rn(t[tx][ty + i]);
}

// ---------------------------------------------------------------------------
// fp16 transpose (per-batch): out[C,R] = in[R,C]^T
// ---------------------------------------------------------------------------
__global__ void transpose_h(const __half* __restrict__ in, __half* __restrict__ out,
                            int R, int C, size_t sIn, size_t sOut)
{
    __shared__ __half t[32][34];
    in  += (size_t)blockIdx.z * sIn;
    out += (size_t)blockIdx.z * sOut;
    const int c0 = blockIdx.x * 32, r0 = blockIdx.y * 32;
    const int tx = threadIdx.x, ty = threadIdx.y;      // 32 x 8
#pragma unroll
    for (int i = 0; i < 32; i += 8)
        t[ty + i][tx] = in[(size_t)(r0 + ty + i) * C + c0 + tx];
    __syncthreads();
#pragma unroll
    for (int i = 0; i < 32; i += 8)
        out[(size_t)(c0 + ty + i) * R + r0 + tx] = t[tx][ty + i];
}

// ---------------------------------------------------------------------------
// Causal softmax: reads fp32 scores, writes fp16 probabilities (tail zeroed).
// ---------------------------------------------------------------------------
__global__ void softmax_causal_kernel(const float* __restrict__ S, __half* __restrict__ P,
                                      int seq, float scale)
{
    const int q = blockIdx.x;
    const size_t roff = ((size_t)blockIdx.y * seq + q) * (size_t)seq;
    const float* row = S + roff;
    __half* prow = P + roff;
    const int L = q + 1;
    const int tid = threadIdx.x;
    __shared__ float redm[8], reds[8];

    float m = -3.4e38f;
    for (int j = tid; j < L; j += 256) m = fmaxf(m, row[j]);
#pragma unroll
    for (int o = 16; o; o >>= 1) m = fmaxf(m, __shfl_xor_sync(0xffffffffu, m, o));
    if ((tid & 31) == 0) redm[tid >> 5] = m;
    __syncthreads();
    m = fmaxf(fmaxf(fmaxf(redm[0], redm[1]), fmaxf(redm[2], redm[3])),
              fmaxf(fmaxf(redm[4], redm[5]), fmaxf(redm[6], redm[7])));

    float s = 0.f;
    for (int j = tid; j < L; j += 256) s += __expf(scale * (row[j] - m));
#pragma unroll
    for (int o = 16; o; o >>= 1) s += __shfl_xor_sync(0xffffffffu, s, o);
    if ((tid & 31) == 0) reds[tid >> 5] = s;
    __syncthreads();
    s = (reds[0] + reds[1]) + (reds[2] + reds[3]) +
        (reds[4] + reds[5]) + (reds[6] + reds[7]);
    const float inv = 1.f / s;

    for (int j = tid; j < seq; j += 256)
        prow[j] = (j < L) ? __float2half_rn(__expf(scale * (row[j] - m)) * inv)
                          : __float2half_rn(0.f);
}

// ---------------------------------------------------------------------------
extern "C" void kernel_launch(void* const* d_in, const int* in_sizes, int n_in,
                              void* d_out, int out_size)
{
    const float* x  = (const float*)d_in[0];
    const float* Wq = (const float*)d_in[1];
    const float* Wk = (const float*)d_in[2];
    const float* Wv = (const float*)d_in[3];
    float* out = (float*)d_out;

    static __half *xh = nullptr, *wth, *qkvh, *vth, *ph;
    static float  *s;
    if (!xh) {   // first call is outside graph capture
        cudaFuncSetAttribute(mma_gemm<0,0,1>, cudaFuncAttributeMaxDynamicSharedMemorySize, SMEM_TOTAL);
        cudaFuncSetAttribute(mma_gemm<1,0,0>, cudaFuncAttributeMaxDynamicSharedMemorySize, SMEM_TOTAL);
        cudaFuncSetAttribute(mma_gemm<0,1,0>, cudaFuncAttributeMaxDynamicSharedMemorySize, SMEM_TOTAL);
        cudaGetSymbolAddress((void**)&xh,   g_xh);
        cudaGetSymbolAddress((void**)&wth,  g_wth);
        cudaGetSymbolAddress((void**)&qkvh, g_qkvh);
        cudaGetSymbolAddress((void**)&vth,  g_vth);
        cudaGetSymbolAddress((void**)&s,    g_s);
        cudaGetSymbolAddress((void**)&ph,   g_ph);
    }
    __half* qh = qkvh;
    __half* kh = qkvh + (size_t)MTOT * DIM;
    __half* vh = qkvh + 2 * (size_t)MTOT * DIM;

    // 0a) x -> fp16
    {
        int n4 = MTOT * DIM / 4;
        f2h_kernel<<<(n4 + 255) / 256, 256>>>((const float4*)x, (uint2*)xh, n4);
    }
    // 0b) W^T -> fp16 (K-major B operands)
    {
        dim3 g(DIM / 32, DIM / 32), b(32, 8);
        transpose_f2h<<<g, b>>>(Wq, wth,                         DIM, DIM);
        transpose_f2h<<<g, b>>>(Wk, wth + (size_t)DIM * DIM,     DIM, DIM);
        transpose_f2h<<<g, b>>>(Wv, wth + 2 * (size_t)DIM * DIM, DIM, DIM);
    }
    // 1) fused projections -> Q,K,V (fp16)
    {
        dim3 g(DIM / TN, MTOT / TM, 3);
        mma_gemm<0,0,1><<<g, 256, SMEM_TOTAL>>>(xh, wth, qkvh, DIM, DIM, DIM, DIM,
                                                0, (size_t)DIM * DIM, (size_t)MTOT * DIM);
    }
    // 2) V^T per batch (fp16)
    {
        dim3 g(DIM / 32, SEQ / 32, BATCH), b(32, 8);
        transpose_h<<<g, b>>>(vh, vth, SEQ, DIM, (size_t)SEQ * DIM, (size_t)SEQ * DIM);
    }
    // 3) scores: S[b] = Q[b] * K[b]^T (fp32 out); skip fully-masked tiles
    {
        dim3 g(SEQ / TN, SEQ / TM, BATCH);
        mma_gemm<1,0,0><<<g, 256, SMEM_TOTAL>>>(qh, kh, s, DIM, DIM, DIM, SEQ,
                                                (size_t)SEQ * DIM, (size_t)SEQ * DIM,
                                                (size_t)SEQ * SEQ);
    }
    // 4) causal softmax (scale 1/32) -> P fp16, tail zeroed
    {
        dim3 g(SEQ, BATCH);
        softmax_causal_kernel<<<g, 256>>>(s, ph, SEQ, 0.03125f);
    }
    // 5) O[b] = P[b] * V[b] (fp32 out), K limited to m0+TM
    {
        dim3 g(DIM / TN, SEQ / TM, BATCH);
        mma_gemm<0,1,0><<<g, 256, SMEM_TOTAL>>>(ph, vth, out, SEQ, SEQ, SEQ, DIM,
                                                (size_t)SEQ * SEQ, (size_t)SEQ * DIM,
                                                (size_t)SEQ * DIM);
    }
}

// round 15
// speedup vs baseline: 5.1601x; 1.0931x over previous
#include <cuda_runtime.h>
#include <cuda_fp16.h>
#include <cstdint>

// ---------------------------------------------------------------- problem
#define BATCH 4
#define SEQ   2048
#define DIM   1024
#define MTOT  (BATCH * SEQ)          // 8192

// ---------------------------------------------------------------- GEMM tile
#define TM   128
#define TN   256
#define BKH  32                      // K halves per stage (2 x k16)
#define SREG 40                      // smem row stride in halves (80 B)
#define ABUF (TM * SREG * 2)         // 10240 B per A stage
#define BBUF (TN * SREG * 2)         // 20480 B per B stage
#define STAGES 3
#define SMEM_TOTAL (STAGES * (ABUF + BBUF))   // 92160 B

// ---------------------------------------------------------------- scratch
__device__ __align__(1024) __half g_xh  [(size_t)MTOT * DIM];        // x fp16
__device__ __align__(1024) __half g_wth [3][(size_t)DIM * DIM];      // W^T fp16
__device__ __align__(1024) __half g_qkvh[3][(size_t)MTOT * DIM];     // Q,K,V fp16
__device__ __align__(1024) __half g_vth [(size_t)MTOT * DIM];        // V^T fp16
__device__ __align__(1024) float  g_s   [(size_t)BATCH * SEQ * SEQ]; // scores fp32
__device__ __align__(1024) __half g_ph  [(size_t)BATCH * SEQ * SEQ]; // P fp16

// ---------------------------------------------------------------- helpers
__device__ __forceinline__ uint32_t f2h2(float lo, float hi) {   // packed {lo,hi}
    uint32_t r; asm("cvt.rn.f16x2.f32 %0, %1, %2;" : "=r"(r) : "f"(hi), "f"(lo)); return r;
}
__device__ __forceinline__ uint32_t smem_u32(const void* p) {
    uint32_t a;
    asm("{ .reg .u64 t; cvta.to.shared.u64 t, %1; cvt.u32.u64 %0, t; }" : "=r"(a) : "l"(p));
    return a;
}
__device__ __forceinline__ void mma_f16(float* d, const uint32_t* a, const uint32_t* b) {
    asm volatile(
        "mma.sync.aligned.m16n8k16.row.col.f32.f16.f16.f32 "
        "{%0,%1,%2,%3}, {%4,%5,%6,%7}, {%8,%9}, {%0,%1,%2,%3};"
        : "+f"(d[0]), "+f"(d[1]), "+f"(d[2]), "+f"(d[3])
        : "r"(a[0]), "r"(a[1]), "r"(a[2]), "r"(a[3]), "r"(b[0]), "r"(b[1]));
}
__device__ __forceinline__ void ldmx4(uint32_t* r, uint32_t addr) {
    asm volatile("ldmatrix.sync.aligned.m8n8.x4.shared.b16 {%0,%1,%2,%3}, [%4];"
                 : "=r"(r[0]), "=r"(r[1]), "=r"(r[2]), "=r"(r[3]) : "r"(addr));
}
__device__ __forceinline__ void cp16(uint32_t dst, const void* src) {
    asm volatile("cp.async.cg.shared.global [%0], [%1], 16;" :: "r"(dst), "l"(src));
}
#define CP_COMMIT() asm volatile("cp.async.commit_group;" ::: "memory")
#define CP_WAIT1()  asm volatile("cp.async.wait_group 1;" ::: "memory")

// ---------------------------------------------------------------------------
// fp16 tensor-core GEMM (fp32 accum): C[M,N] = A[M,K] * B[N,K]^T.
// A,B fp16 K-major in gmem. CTA 128x256, warp tile 64x64, 8 warps, BK=32.
// 3-stage cp.async pipeline: wait_group(1) -> barrier -> issue stage it+2
// (into the buffer whose readers just finished) -> mma on stage it.
// HOUT: write C as fp16 (else fp32). CAUSAL / KLIM as before.
// ---------------------------------------------------------------------------
template <int CAUSAL, int KLIM, int HOUT>
__global__ __launch_bounds__(256, 1)
void mma_gemm(const __half* __restrict__ A, const __half* __restrict__ B,
              void* __restrict__ Cv, int K, int lda, int ldb, int ldc,
              size_t sA, size_t sB, size_t sC)
{
    const int m0 = blockIdx.y * TM;
    const int n0 = blockIdx.x * TN;
    if (CAUSAL && n0 > m0 + TM - 1) return;

    A += (size_t)blockIdx.z * sA;
    B += (size_t)blockIdx.z * sB;

    const int kend  = KLIM ? (m0 + TM) : K;
    const int niter = kend / BKH;            // >= 4 always

    extern __shared__ __align__(16) char smem[];
    const uint32_t AsB = smem_u32(smem);                    // STAGES x ABUF
    const uint32_t BsB = AsB + STAGES * ABUF;               // STAGES x BBUF

    const int tid    = threadIdx.x;
    const int lane   = tid & 31;
    const int wid    = tid >> 5;
    const int warp_m = (wid & 1) * 64;
    const int warp_n = (wid >> 1) * 64;
    const int gid    = lane >> 2;
    const int tig    = lane & 3;

    // ldmatrix lane addressing (validated in R7-R9)
    const int msel = lane >> 3, mrow = lane & 7;
    const uint32_t off  = (((msel & 1) * 8 + mrow) * SREG + (msel >> 1) * 8) * 2;
    const uint32_t offA = warp_m * SREG * 2 + off;
    const uint32_t offB = warp_n * SREG * 2 + off;

    // cp.async chunk mapping: 16B chunks; row = tid>>2, col16 = tid&3
    const int crow = tid >> 2;               // 0..63
    const int ccol = tid & 3;                // 0..3
    const uint32_t dA0 = (crow * SREG + ccol * 8) * 2;          // bytes in stage
    const uint32_t dA1 = ((crow + 64) * SREG + ccol * 8) * 2;
    const __half* gA0 = A + (size_t)(m0 + crow)      * lda + ccol * 8;
    const __half* gA1 = A + (size_t)(m0 + crow + 64) * lda + ccol * 8;
    const __half* gB[4] = {
        B + (size_t)(n0 + crow)       * ldb + ccol * 8,
        B + (size_t)(n0 + crow + 64)  * ldb + ccol * 8,
        B + (size_t)(n0 + crow + 128) * ldb + ccol * 8,
        B + (size_t)(n0 + crow + 192) * ldb + ccol * 8 };

    float acc[4][8][4];
#pragma unroll
    for (int i = 0; i < 4; i++)
#pragma unroll
        for (int j = 0; j < 8; j++)
#pragma unroll
            for (int r = 0; r < 4; r++) acc[i][j][r] = 0.f;

    // prologue: stages 0,1
#pragma unroll
    for (int s = 0; s < STAGES - 1; ++s) {
        const int ko = s * BKH;
        const uint32_t aD = AsB + s * ABUF, bD = BsB + s * BBUF;
        cp16(aD + dA0, gA0 + ko);
        cp16(aD + dA1, gA1 + ko);
#pragma unroll
        for (int r = 0; r < 4; ++r)
            cp16(bD + dA0 + (r * 64) * SREG * 2, gB[r] + ko);
        CP_COMMIT();
    }

    for (int it = 0; it < niter; ++it) {
        CP_WAIT1();                  // stage it complete (<=1 group pending)
        __syncthreads();             // data visible CTA-wide; prior readers done

        // issue stage it+2 into buffer (it+2)%3 (freed by the barrier above)
        if (it + 2 < niter) {
            const int s = (it + 2) % STAGES;
            const int ko = (it + 2) * BKH;
            const uint32_t aD = AsB + s * ABUF, bD = BsB + s * BBUF;
            cp16(aD + dA0, gA0 + ko);
            cp16(aD + dA1, gA1 + ko);
#pragma unroll
            for (int r = 0; r < 4; ++r)
                cp16(bD + dA0 + (r * 64) * SREG * 2, gB[r] + ko);
        }
        CP_COMMIT();                 // one commit per iter keeps group accounting

        const uint32_t aBuf = AsB + (it % STAGES) * ABUF;
        const uint32_t bBuf = BsB + (it % STAGES) * BBUF;
#pragma unroll
        for (int kc = 0; kc < 2; ++kc) {
            uint32_t af[4][4], bf[8][2];
#pragma unroll
            for (int i = 0; i < 4; ++i)
                ldmx4(af[i], aBuf + offA + i * (16 * SREG * 2) + kc * 32);
#pragma unroll
            for (int jp = 0; jp < 4; ++jp) {
                uint32_t r[4];
                ldmx4(r, bBuf + offB + jp * (16 * SREG * 2) + kc * 32);
                bf[2 * jp][0]     = r[0]; bf[2 * jp + 1][0] = r[1];
                bf[2 * jp][1]     = r[2]; bf[2 * jp + 1][1] = r[3];
            }
#pragma unroll
            for (int i = 0; i < 4; ++i)
#pragma unroll
                for (int j = 0; j < 8; ++j)
                    mma_f16(acc[i][j], af[i], bf[j]);
        }
    }

    // epilogue
    if (HOUT) {
        __half* Ch = (__half*)Cv + (size_t)blockIdx.z * sC;
#pragma unroll
        for (int i = 0; i < 4; ++i) {
            const int r0 = m0 + warp_m + i * 16 + gid;
#pragma unroll
            for (int j = 0; j < 8; ++j) {
                const int c0 = n0 + warp_n + j * 8 + 2 * tig;
                *(uint32_t*)(Ch + (size_t)(r0)     * ldc + c0) = f2h2(acc[i][j][0], acc[i][j][1]);
                *(uint32_t*)(Ch + (size_t)(r0 + 8) * ldc + c0) = f2h2(acc[i][j][2], acc[i][j][3]);
            }
        }
    } else {
        float* Cf = (float*)Cv + (size_t)blockIdx.z * sC;
#pragma unroll
        for (int i = 0; i < 4; ++i) {
            const int r0 = m0 + warp_m + i * 16 + gid;
#pragma unroll
            for (int j = 0; j < 8; ++j) {
                const int c0 = n0 + warp_n + j * 8 + 2 * tig;
                *(float2*)(Cf + (size_t)(r0)     * ldc + c0) = make_float2(acc[i][j][0], acc[i][j][1]);
                *(float2*)(Cf + (size_t)(r0 + 8) * ldc + c0) = make_float2(acc[i][j][2], acc[i][j][3]);
            }
        }
    }
}

// ---------------------------------------------------------------------------
__global__ void f2h_kernel(const float4* __restrict__ in, uint2* __restrict__ out, int n4)
{
    int i = blockIdx.x * blockDim.x + threadIdx.x;
    if (i < n4) {
        float4 v = in[i];
        out[i] = make_uint2(f2h2(v.x, v.y), f2h2(v.z, v.w));
    }
}

__global__ void transpose_f2h(const float* __restrict__ in, __half* __restrict__ out,
                              int R, int C)
{
    __shared__ float t[32][33];
    const int c0 = blockIdx.x * 32, r0 = blockIdx.y * 32;
    const int tx = threadIdx.x, ty = threadIdx.y;
#pragma unroll
    for (int i = 0; i < 32; i += 8)
        t[ty + i][tx] = in[(size_t)(r0 + ty + i) * C + c0 + tx];
    __syncthreads();
#pragma unroll
    for (int i = 0; i < 32; i += 8)
        out[(size_t)(c0 + ty + i) * R + r0 + tx] = __float2half_rn(t[tx][ty + i]);
}

__global__ void transpose_h(const __half* __restrict__ in, __half* __restrict__ out,
                            int R, int C, size_t sIn, size_t sOut)
{
    __shared__ __half t[32][34];
    in  += (size_t)blockIdx.z * sIn;
    out += (size_t)blockIdx.z * sOut;
    const int c0 = blockIdx.x * 32, r0 = blockIdx.y * 32;
    const int tx = threadIdx.x, ty = threadIdx.y;
#pragma unroll
    for (int i = 0; i < 32; i += 8)
        t[ty + i][tx] = in[(size_t)(r0 + ty + i) * C + c0 + tx];
    __syncthreads();
#pragma unroll
    for (int i = 0; i < 32; i += 8)
        out[(size_t)(c0 + ty + i) * R + r0 + tx] = t[tx][ty + i];
}

// ---------------------------------------------------------------------------
// Causal softmax, vectorized: fp32 scores (float4) -> fp16 probs (uint2),
// masked tail zeroed. One block (256 threads) per row.
// ---------------------------------------------------------------------------
__global__ void softmax_causal_kernel(const float* __restrict__ S, __half* __restrict__ P,
                                      int seq, float scale)
{
    const int q = blockIdx.x;
    const size_t roff = ((size_t)blockIdx.y * seq + q) * (size_t)seq;
    const float4* row4 = (const float4*)(S + roff);
    uint2* prow4 = (uint2*)(P + roff);
    const int L = q + 1;
    const int n4 = seq / 4;
    const int tid = threadIdx.x;
    __shared__ float redm[8], reds[8];

    float m = -3.4e38f;
    for (int j = tid; j < n4; j += 256) {
        const int i0 = j * 4;
        if (i0 >= L) break;
        float4 v = row4[j];
        float a = (i0     < L) ? v.x : -3.4e38f;
        float b = (i0 + 1 < L) ? v.y : -3.4e38f;
        float c = (i0 + 2 < L) ? v.z : -3.4e38f;
        float d = (i0 + 3 < L) ? v.w : -3.4e38f;
        m = fmaxf(m, fmaxf(fmaxf(a, b), fmaxf(c, d)));
    }
#pragma unroll
    for (int o = 16; o; o >>= 1) m = fmaxf(m, __shfl_xor_sync(0xffffffffu, m, o));
    if ((tid & 31) == 0) redm[tid >> 5] = m;
    __syncthreads();
    m = fmaxf(fmaxf(fmaxf(redm[0], redm[1]), fmaxf(redm[2], redm[3])),
              fmaxf(fmaxf(redm[4], redm[5]), fmaxf(redm[6], redm[7])));

    float s = 0.f;
    for (int j = tid; j < n4; j += 256) {
        const int i0 = j * 4;
        if (i0 >= L) break;
        float4 v = row4[j];
        if (i0     < L) s += __expf(scale * (v.x - m));
        if (i0 + 1 < L) s += __expf(scale * (v.y - m));
        if (i0 + 2 < L) s += __expf(scale * (v.z - m));
        if (i0 + 3 < L) s += __expf(scale * (v.w - m));
    }
#pragma unroll
    for (int o = 16; o; o >>= 1) s += __shfl_xor_sync(0xffffffffu, s, o);
    if ((tid & 31) == 0) reds[tid >> 5] = s;
    __syncthreads();
    s = (reds[0] + reds[1]) + (reds[2] + reds[3]) +
        (reds[4] + reds[5]) + (reds[6] + reds[7]);
    const float inv = 1.f / s;

    for (int j = tid; j < n4; j += 256) {
        const int i0 = j * 4;
        float4 v = row4[j];
        float p0 = (i0     < L) ? __expf(scale * (v.x - m)) * inv : 0.f;
        float p1 = (i0 + 1 < L) ? __expf(scale * (v.y - m)) * inv : 0.f;
        float p2 = (i0 + 2 < L) ? __expf(scale * (v.z - m)) * inv : 0.f;
        float p3 = (i0 + 3 < L) ? __expf(scale * (v.w - m)) * inv : 0.f;
        prow4[j] = make_uint2(f2h2(p0, p1), f2h2(p2, p3));
    }
}

// ---------------------------------------------------------------------------
extern "C" void kernel_launch(void* const* d_in, const int* in_sizes, int n_in,
                              void* d_out, int out_size)
{
    const float* x  = (const float*)d_in[0];
    const float* Wq = (const float*)d_in[1];
    const float* Wk = (const float*)d_in[2];
    const float* Wv = (const float*)d_in[3];
    float* out = (float*)d_out;

    static __half *xh = nullptr, *wth, *qkvh, *vth, *ph;
    static float  *s;
    if (!xh) {   // first call is outside graph capture
        cudaFuncSetAttribute(mma_gemm<0,0,1>, cudaFuncAttributeMaxDynamicSharedMemorySize, SMEM_TOTAL);
        cudaFuncSetAttribute(mma_gemm<1,0,0>, cudaFuncAttributeMaxDynamicSharedMemorySize, SMEM_TOTAL);
        cudaFuncSetAttribute(mma_gemm<0,1,0>, cudaFuncAttributeMaxDynamicSharedMemorySize, SMEM_TOTAL);
        cudaGetSymbolAddress((void**)&xh,   g_xh);
        cudaGetSymbolAddress((void**)&wth,  g_wth);
        cudaGetSymbolAddress((void**)&qkvh, g_qkvh);
        cudaGetSymbolAddress((void**)&vth,  g_vth);
        cudaGetSymbolAddress((void**)&s,    g_s);
        cudaGetSymbolAddress((void**)&ph,   g_ph);
    }
    __half* qh = qkvh;
    __half* kh = qkvh + (size_t)MTOT * DIM;
    __half* vh = qkvh + 2 * (size_t)MTOT * DIM;

    // 0a) x -> fp16
    {
        int n4 = MTOT * DIM / 4;
        f2h_kernel<<<(n4 + 255) / 256, 256>>>((const float4*)x, (uint2*)xh, n4);
    }
    // 0b) W^T -> fp16 (K-major B operands)
    {
        dim3 g(DIM / 32, DIM / 32), b(32, 8);
        transpose_f2h<<<g, b>>>(Wq, wth,                         DIM, DIM);
        transpose_f2h<<<g, b>>>(Wk, wth + (size_t)DIM * DIM,     DIM, DIM);
        transpose_f2h<<<g, b>>>(Wv, wth + 2 * (size_t)DIM * DIM, DIM, DIM);
    }
    // 1) fused projections -> Q,K,V (fp16)
    {
        dim3 g(DIM / TN, MTOT / TM, 3);
        mma_gemm<0,0,1><<<g, 256, SMEM_TOTAL>>>(xh, wth, qkvh, DIM, DIM, DIM, DIM,
                                                0, (size_t)DIM * DIM, (size_t)MTOT * DIM);
    }
    // 2) V^T per batch (fp16)
    {
        dim3 g(DIM / 32, SEQ / 32, BATCH), b(32, 8);
        transpose_h<<<g, b>>>(vh, vth, SEQ, DIM, (size_t)SEQ * DIM, (size_t)SEQ * DIM);
    }
    // 3) scores: S[b] = Q[b] * K[b]^T (fp32 out); skip fully-masked tiles
    {
        dim3 g(SEQ / TN, SEQ / TM, BATCH);
        mma_gemm<1,0,0><<<g, 256, SMEM_TOTAL>>>(qh, kh, s, DIM, DIM, DIM, SEQ,
                                                (size_t)SEQ * DIM, (size_t)SEQ * DIM,
                                                (size_t)SEQ * SEQ);
    }
    // 4) causal softmax (scale 1/32) -> P fp16, tail zeroed
    {
        dim3 g(SEQ, BATCH);
        softmax_causal_kernel<<<g, 256>>>(s, ph, SEQ, 0.03125f);
    }
    // 5) O[b] = P[b] * V[b] (fp32 out), K limited to m0+TM
    {
        dim3 g(DIM / TN, SEQ / TM, BATCH);
        mma_gemm<0,1,0><<<g, 256, SMEM_TOTAL>>>(ph, vth, out, SEQ, SEQ, SEQ, DIM,
                                                (size_t)SEQ * SEQ, (size_t)SEQ * DIM,
                                                (size_t)SEQ * DIM);
    }
}